// round 17
// baseline (speedup 1.0000x reference)
#include <cuda_runtime.h>
#include <cstdint>

#define B     32
#define C     9
#define NA    65440
#define TILE  384
#define TPB   171                 // ceil(65440/384); last tile = 160 anchors
#define LAST_CNT (NA - (TPB - 1) * TILE)   // 160
#define NTILES (B * TPB)          // 5472
#define NCTA  296                 // 2 CTAs/SM * 148 SMs (persistent)
#define BLOCK 384                 // 1 anchor/thread
#define NSTAGE 3                  // TWO fills in flight per CTA (R16 had one)
#define SCALE_XY 10.0f
#define SCALE_WH 5.0f
#define ALPHA_SUM 8010.0f         // 10 + 8*1000

// per-stage SMEM layout (bytes), TILE=384
#define OFF_CONF 0                // 9 * 384 * 4 = 13824
#define OFF_BD   13824            // 4 * 384 * 4 =  6144
#define OFF_AN   19968            // 4 * 384 * 4 =  6144
#define OFF_GT   26112            // 384 * 16    =  6144
#define OFF_LAB  32256            // 384 * 4     =  1536
#define STAGE_BYTES 33792
#define SMEM_STAGE0 128           // 3 mbarriers live in [0,24)
#define SMEM_TOTAL (SMEM_STAGE0 + NSTAGE * STAGE_BYTES)   // 101504 (x2 CTA = 203KB/SM)

__device__ float g_focal[NCTA];
__device__ float g_reg[NCTA];
__device__ int   g_pos[NCTA];
__device__ int   g_ticket;        // zero-init; last block resets -> replay-safe

__device__ __forceinline__ uint32_t s2u(const void* p) {
    uint32_t a;
    asm("{ .reg .u64 t; cvta.to.shared.u64 t, %1; cvt.u32.u64 %0, t; }" : "=r"(a) : "l"(p));
    return a;
}
__device__ __forceinline__ void mbar_init(uint32_t m, uint32_t n) {
    asm volatile("mbarrier.init.shared.b64 [%0], %1;" :: "r"(m), "r"(n) : "memory");
}
__device__ __forceinline__ void mbar_expect(uint32_t m, uint32_t bytes) {
    asm volatile("mbarrier.arrive.expect_tx.shared.b64 _, [%0], %1;" :: "r"(m), "r"(bytes) : "memory");
}
__device__ __forceinline__ void bulk_g2s(uint32_t dst, const void* src, uint32_t bytes, uint32_t m) {
    asm volatile("cp.async.bulk.shared::cluster.global.mbarrier::complete_tx::bytes [%0], [%1], %2, [%3];"
                 :: "r"(dst), "l"(src), "r"(bytes), "r"(m) : "memory");
}
__device__ __forceinline__ void mbar_wait(uint32_t m, uint32_t parity) {
    asm volatile("{\n\t"
                 ".reg .pred P;\n\t"
                 "W_%=:\n\t"
                 "mbarrier.try_wait.parity.acquire.cta.shared::cta.b64 P, [%0], %1, 0x989680;\n\t"
                 "@P bra D_%=;\n\t"
                 "bra W_%=;\n\t"
                 "D_%=:\n\t"
                 "}" :: "r"(m), "r"(parity) : "memory");
}
__device__ __forceinline__ float warpReduceF(float v) {
    #pragma unroll
    for (int o = 16; o > 0; o >>= 1) v += __shfl_down_sync(0xffffffffu, v, o);
    return v;
}
__device__ __forceinline__ int warpReduceI(int v) {
    #pragma unroll
    for (int o = 16; o > 0; o >>= 1) v += __shfl_down_sync(0xffffffffu, v, o);
    return v;
}

// One elected thread issues the whole tile as 19 bulk copies.
// Batch-minor tile order keeps the anchors rows L2-hot across batches.
__device__ __forceinline__ void issue_tile(
    int t, char* stage, uint32_t mbar,
    const float* bbox_delta, const float* confs, const float* gt_bbox,
    const int* gt_labels, const float* anchors)
{
    const int b = t & (B - 1);
    const int x = t >> 5;
    const int cnt = (x == TPB - 1) ? LAST_CNT : TILE;
    const size_t aoff = (size_t)x * TILE;
    const uint32_t st = s2u(stage);
    const uint32_t cb = (uint32_t)cnt * 4;

    mbar_expect(mbar, (uint32_t)cnt * 88);
    #pragma unroll
    for (int c = 0; c < C; c++)
        bulk_g2s(st + OFF_CONF + c * (TILE * 4),
                 confs + ((size_t)b * C + c) * NA + aoff, cb, mbar);
    #pragma unroll
    for (int c = 0; c < 4; c++)
        bulk_g2s(st + OFF_BD + c * (TILE * 4),
                 bbox_delta + ((size_t)b * 4 + c) * NA + aoff, cb, mbar);
    #pragma unroll
    for (int c = 0; c < 4; c++)
        bulk_g2s(st + OFF_AN + c * (TILE * 4),
                 anchors + (size_t)c * NA + aoff, cb, mbar);
    bulk_g2s(st + OFF_GT, gt_bbox + ((size_t)b * NA + aoff) * 4, (uint32_t)cnt * 16, mbar);
    bulk_g2s(st + OFF_LAB, gt_labels + (size_t)b * NA + aoff, cb, mbar);
}

__global__ void __launch_bounds__(BLOCK, 2)
ssd_loss_bulk(const float* __restrict__ bbox_delta,
              const float* __restrict__ confs,
              const float* __restrict__ gt_bbox,
              const int*   __restrict__ gt_labels,
              const float* __restrict__ anchors,
              float*       __restrict__ out) {
    extern __shared__ char smem[];
    const int tid = threadIdx.x;
    uint32_t mb[NSTAGE];
    char* stg[NSTAGE];
    #pragma unroll
    for (int s = 0; s < NSTAGE; s++) {
        mb[s]  = s2u(smem + s * 8);
        stg[s] = smem + SMEM_STAGE0 + s * STAGE_BYTES;
    }

    if (tid == 0) {
        #pragma unroll
        for (int s = 0; s < NSTAGE; s++) mbar_init(mb[s], 1);
    }
    __syncthreads();

    float focal_acc = 0.0f;
    float reg_acc   = 0.0f;
    int   pos_acc   = 0;

    // prologue: fill slots 0 and 1 (two fills in flight)
    if (tid == 0) {
        if (blockIdx.x < NTILES)
            issue_tile(blockIdx.x, stg[0], mb[0],
                       bbox_delta, confs, gt_bbox, gt_labels, anchors);
        if (blockIdx.x + NCTA < NTILES)
            issue_tile(blockIdx.x + NCTA, stg[1], mb[1],
                       bbox_delta, confs, gt_bbox, gt_labels, anchors);
    }

    int k = 0;
    for (int t = blockIdx.x; t < NTILES; t += NCTA, k++) {
        const int slot = k % NSTAGE;
        const uint32_t par = (uint32_t)((k / NSTAGE) & 1);
        char* st = stg[slot];

        // prefetch distance 2: fill slot (k+2)%3, whose previous consumers
        // finished at the __syncthreads ending iteration k-1
        int tn = t + 2 * NCTA;
        if (tid == 0 && tn < NTILES) {
            int sn = (k + 2) % NSTAGE;
            issue_tile(tn, stg[sn], mb[sn],
                       bbox_delta, confs, gt_bbox, gt_labels, anchors);
        }

        mbar_wait(mb[slot], par);   // acquire: smem tile visible

        const int x = t >> 5;
        const int cnt = (x == TPB - 1) ? LAST_CNT : TILE;

        if (tid < cnt) {                  // ONE anchor per thread
            const float* sf = reinterpret_cast<const float*>(st);
            const int lab = *reinterpret_cast<const int*>(st + OFF_LAB + tid * 4);

            // --- focal loss (unnormalized softmax; validated rel_err 0) ---
            float s = 0.0f, ct = 0.0f;
            #pragma unroll
            for (int c = 0; c < C; c++) {
                float x0 = sf[(OFF_CONF / 4) + c * TILE + tid];
                s += __expf(x0);
                if (lab == c) ct = x0;
            }
            float logp_t = ct - __logf(s);
            float p_t    = __expf(logp_t);
            float om     = 1.0f - p_t;
            focal_acc += om * om * om * logp_t;

            // --- regression ---
            if (lab > 0) {
                pos_acc++;
                float an0 = sf[(OFF_AN / 4) + 0 * TILE + tid];
                float an1 = sf[(OFF_AN / 4) + 1 * TILE + tid];
                float an2 = sf[(OFF_AN / 4) + 2 * TILE + tid];
                float an3 = sf[(OFF_AN / 4) + 3 * TILE + tid];
                float4 g = *reinterpret_cast<const float4*>(st + OFF_GT + tid * 16);
                float inv_w = 1.0f / an2;
                float inv_h = 1.0f / an3;
                float gl0 = SCALE_XY * (g.x - an0) * inv_w;
                float gl1 = SCALE_XY * (g.y - an1) * inv_h;
                float gl2 = SCALE_WH * __logf(g.z * inv_w);
                float gl3 = SCALE_WH * __logf(g.w * inv_h);
                float ds[4] = {
                    sf[(OFF_BD / 4) + 0 * TILE + tid] - gl0,
                    sf[(OFF_BD / 4) + 1 * TILE + tid] - gl1,
                    sf[(OFF_BD / 4) + 2 * TILE + tid] - gl2,
                    sf[(OFF_BD / 4) + 3 * TILE + tid] - gl3
                };
                #pragma unroll
                for (int c = 0; c < 4; c++) {
                    float ad = fabsf(ds[c]);
                    reg_acc += (ad < 1.0f) ? 0.5f * ds[c] * ds[c] : ad - 0.5f;
                }
            }
        }
        __syncthreads();   // all readers done with this slot before refill
    }

    // ============ one block reduction per CTA ============
    __shared__ float sF[BLOCK / 32];
    __shared__ float sR[BLOCK / 32];
    __shared__ int   sP[BLOCK / 32];
    __shared__ int   sLast;
    int lane = tid & 31;
    int wid  = tid >> 5;

    focal_acc = warpReduceF(focal_acc);
    reg_acc   = warpReduceF(reg_acc);
    pos_acc   = warpReduceI(pos_acc);
    if (lane == 0) { sF[wid] = focal_acc; sR[wid] = reg_acc; sP[wid] = pos_acc; }
    __syncthreads();
    if (wid == 0) {
        float f = (lane < BLOCK / 32) ? sF[lane] : 0.0f;
        float r = (lane < BLOCK / 32) ? sR[lane] : 0.0f;
        int   p = (lane < BLOCK / 32) ? sP[lane] : 0;
        f = warpReduceF(f);
        r = warpReduceF(r);
        p = warpReduceI(p);
        if (lane == 0) {
            g_focal[blockIdx.x] = f;
            g_reg[blockIdx.x]   = r;
            g_pos[blockIdx.x]   = p;
            __threadfence();
            int tk = atomicAdd(&g_ticket, 1);
            sLast = (tk == NCTA - 1) ? 1 : 0;
        }
    }
    __syncthreads();

    // ============ last CTA folds the 296 partials ============
    if (sLast) {
        float f = 0.0f, r = 0.0f;
        int   p = 0;
        for (int i = tid; i < NCTA; i += BLOCK) {
            f += g_focal[i];
            r += g_reg[i];
            p += g_pos[i];
        }
        f = warpReduceF(f); r = warpReduceF(r); p = warpReduceI(p);
        if (lane == 0) { sF[wid] = f; sR[wid] = r; sP[wid] = p; }
        __syncthreads();
        if (wid == 0) {
            f = (lane < BLOCK / 32) ? sF[lane] : 0.0f;
            r = (lane < BLOCK / 32) ? sR[lane] : 0.0f;
            p = (lane < BLOCK / 32) ? sP[lane] : 0;
            f = warpReduceF(f); r = warpReduceF(r); p = warpReduceI(p);
            if (lane == 0) {
                float cls = -ALPHA_SUM * f / (float)((size_t)B * NA);
                out[0] = r / (float)p + cls;
                g_ticket = 0;   // reset for next graph replay
            }
        }
    }
}

extern "C" void kernel_launch(void* const* d_in, const int* in_sizes, int n_in,
                              void* d_out, int out_size) {
    const float* bbox_delta = (const float*)d_in[0];
    const float* confs      = (const float*)d_in[1];
    const float* gt_bbox    = (const float*)d_in[2];
    const int*   gt_labels  = (const int*)d_in[3];
    const float* anchors    = (const float*)d_in[4];

    static int attr_done = 0;   // host-side idempotent opt-in (no device alloc)
    if (!attr_done) {
        cudaFuncSetAttribute(ssd_loss_bulk,
                             cudaFuncAttributeMaxDynamicSharedMemorySize, SMEM_TOTAL);
        attr_done = 1;
    }
    ssd_loss_bulk<<<NCTA, BLOCK, SMEM_TOTAL>>>(bbox_delta, confs, gt_bbox, gt_labels,
                                               anchors, (float*)d_out);
}